// round 1
// baseline (speedup 1.0000x reference)
#include <cuda_runtime.h>
#include <cuda_bf16.h>

// out[i,j,:] = W[:,p] + W[:,66+t] + e*W[:,132] + W[:,133+s]
//   p  = same_chain ? clip(res_i-res_j+32,0,64) : 65
//   t  = (same_chain && res_i==res_j) ? clip(tok_i-tok_j+32,0,64) : 65
//   e  = (ent_i==ent_j)
//   s  = e ? clip(sym_i-sym_j+2,0,4) : 5
//
// Table layout (138 rows x 128 channels, channel-contiguous):
//   row r in [0,132): W[c*139 + r]            (covers p-bins 0..65 and t-bins 66..131)
//   row 132+k:        W[c*139+133+k] + (k<5 ? W[c*139+132] : 0)   (entity flag folded in)

#define N_TBL_ROWS 138
#define CZ 128
#define NO_BINS 139
#define THREADS 256

__device__ float g_tbl[N_TBL_ROWS * CZ];

__global__ void build_tbl_kernel(const float* __restrict__ W) {
    int idx = blockIdx.x * blockDim.x + threadIdx.x;
    if (idx >= N_TBL_ROWS * CZ) return;
    int row = idx >> 7;        // 0..137
    int c   = idx & (CZ - 1);  // 0..127
    float v;
    if (row < 132) {
        v = W[c * NO_BINS + row];
    } else {
        int k = row - 132;     // 0..5
        v = W[c * NO_BINS + 133 + k];
        if (k < 5) v += W[c * NO_BINS + 132];
    }
    g_tbl[idx] = v;
}

__global__ __launch_bounds__(THREADS) void relpos_kernel(
    const int* __restrict__ asym,
    const int* __restrict__ res,
    const int* __restrict__ ent,
    const int* __restrict__ tok,
    const int* __restrict__ sym,
    float* __restrict__ out,
    int N)
{
    extern __shared__ float smem[];
    float*    s_tbl = smem;                                   // 138*128 floats
    unsigned* s_idx = (unsigned*)(smem + N_TBL_ROWS * CZ);    // N packed indices

    const int tid = threadIdx.x;
    const int i   = blockIdx.x;

    // --- Prologue A: copy table into SMEM (coalesced float4, conflict-free STS) ---
    {
        float4*       dst = (float4*)s_tbl;
        const float4* src = (const float4*)g_tbl;
        #pragma unroll
        for (int k = tid; k < (N_TBL_ROWS * CZ) / 4; k += THREADS) dst[k] = src[k];
    }

    // --- Prologue B: per-j packed indices for this row i ---
    const int ai = __ldg(asym + i);
    const int ri = __ldg(res  + i);
    const int ei = __ldg(ent  + i);
    const int ti = __ldg(tok  + i);
    const int si = __ldg(sym  + i);

    for (int j = tid; j < N; j += THREADS) {
        int aj = __ldg(asym + j);
        int rj = __ldg(res  + j);
        int ej = __ldg(ent  + j);
        int tj = __ldg(tok  + j);
        int sj = __ldg(sym  + j);

        bool sc = (ai == aj);
        int d  = min(max(ri - rj + 32, 0), 64);
        int p  = sc ? d : 65;

        int dt  = min(max(ti - tj + 32, 0), 64);
        int t66 = (sc && (ri == rj)) ? (66 + dt) : (66 + 65);

        int ds = min(max(si - sj + 2, 0), 4);
        int ch = (ei == ej) ? (132 + ds) : 137;

        s_idx[j] = (unsigned)p | ((unsigned)t66 << 8) | ((unsigned)ch << 16);
    }
    __syncthreads();

    // --- Hot loop: warp-per-pair. 1 LDS scalar + 3 LDS.128 + 1 STG.128 per pair ---
    const int warp = tid >> 5;
    const int lane = tid & 31;
    const float4* tbl4 = (const float4*)s_tbl;
    float* orow = out + (size_t)i * N * CZ + lane * 4;

    #pragma unroll 4
    for (int j = warp; j < N; j += (THREADS / 32)) {
        unsigned pk = s_idx[j];
        int p  = pk & 0xFF;
        int t  = (pk >> 8) & 0xFF;
        int ch = pk >> 16;

        float4 a = tbl4[p  * 32 + lane];
        float4 b = tbl4[t  * 32 + lane];
        float4 c = tbl4[ch * 32 + lane];

        float4 o;
        o.x = a.x + b.x + c.x;
        o.y = a.y + b.y + c.y;
        o.z = a.z + b.z + c.z;
        o.w = a.w + b.w + c.w;

        __stcs((float4*)(orow + (size_t)j * CZ), o);
    }
}

extern "C" void kernel_launch(void* const* d_in, const int* in_sizes, int n_in,
                              void* d_out, int out_size) {
    const int*   asym = (const int*)d_in[0];
    const int*   res  = (const int*)d_in[1];
    const int*   ent  = (const int*)d_in[2];
    const int*   tok  = (const int*)d_in[3];
    const int*   sym  = (const int*)d_in[4];
    const float* W    = (const float*)d_in[5];
    float*       out  = (float*)d_out;

    const int N = in_sizes[0];  // 1024

    // Build the fused bin table (tiny; W stays L2-resident between kernels).
    build_tbl_kernel<<<(N_TBL_ROWS * CZ + 255) / 256, 256>>>(W);

    const int smem_bytes = N_TBL_ROWS * CZ * (int)sizeof(float) + N * (int)sizeof(unsigned);
    cudaFuncSetAttribute(relpos_kernel, cudaFuncAttributeMaxDynamicSharedMemorySize, smem_bytes);
    relpos_kernel<<<N, THREADS, smem_bytes>>>(asym, res, ent, tok, sym, out, N);
}